// round 14
// baseline (speedup 1.0000x reference)
#include <cuda_runtime.h>
#include <cuda_fp16.h>
#include <math.h>
#include <cstdint>

#define N_TOK   8192
#define DM      256
#define NE      16
#define NVIEW   3
#define TOPK    4
#define HID     1024
#define TM      64

// ---- ffn smem layout (32-bit word indices) ----
#define XP_U    0           // X fp16 A-frag: [4mt][16ks][32lane][4] uints = 8192
#define HP_U    8192        // H fp16 A-frag DOUBLE buffer: 2 x 4096 uints = 8192
#define B1_F    16384       // 1024 floats
#define B2_F    17408       // 256
#define TOK_F   17664       // 64 ints
#define GATE_F  17728       // 64
#define SMEM_WORDS 17792
#define SMEM_BYTES (SMEM_WORDS * 4)    // 71168 -> 2 blocks/SM

// ---------------- device scratch ----------------
__device__ int   g_cnt [NVIEW * NE];
__device__ int   g_tok [NVIEW * NE * N_TOK];
__device__ float g_gate[NVIEW * NE * N_TOK];
__device__ uint2 g_w1h [NE * 65536];   // W1 fp16 B-frag order, 8 MB
__device__ uint2 g_w2h [NE * 65536];   // W2 fp16 B-frag order, 8 MB

// ---------------- helpers ----------------
__device__ __forceinline__ uint32_t pk(float lo, float hi) {
    __half2 h = __floats2half2_rn(lo, hi);   // .x = lo (low 16 bits)
    return *reinterpret_cast<uint32_t*>(&h);
}
__device__ __forceinline__ float d4(float4 a, float4 b) {
    return a.x * b.x + a.y * b.y + a.z * b.z + a.w * b.w;
}
__device__ __forceinline__ float wredsum(float x) {
#pragma unroll
    for (int o = 16; o > 0; o >>= 1) x += __shfl_xor_sync(0xffffffffu, x, o);
    return x;
}
__device__ __forceinline__ float gelu_exact(float x) {
    return 0.5f * x * (1.0f + erff(x * 0.70710678118654752440f));
}
// m16n8k16 fp16 mma, fp32 accumulate: D += A*B
__device__ __forceinline__ void mma16(float4& d, const uint4& a,
                                      uint32_t b0, uint32_t b1) {
    asm volatile(
        "mma.sync.aligned.m16n8k16.row.col.f32.f16.f16.f32 "
        "{%0,%1,%2,%3}, {%4,%5,%6,%7}, {%8,%9}, {%0,%1,%2,%3};"
        : "+f"(d.x), "+f"(d.y), "+f"(d.z), "+f"(d.w)
        : "r"(a.x), "r"(a.y), "r"(a.z), "r"(a.w), "r"(b0), "r"(b1));
}
__device__ __forceinline__ void red2(float* p, float a, float b) {
    asm volatile("red.global.add.v2.f32 [%0], {%1, %2};"
                 :: "l"(p), "f"(a), "f"(b) : "memory");
}

// ---- merged kernel 0: prep (blocks 0..1535) + router (blocks 1536..4607) ---
// g_cnt must be zeroed by a prior memset (done in kernel_launch).
__global__ void prep_router_kernel(const float* __restrict__ W1,
                                   const float* __restrict__ W2,
                                   const float* __restrict__ v0,
                                   const float* __restrict__ v1,
                                   const float* __restrict__ v2,
                                   const float* __restrict__ rw,
                                   const float* __restrict__ keys,
                                   float* __restrict__ out) {
    __shared__ float s[9216];
    int tid = threadIdx.x, b = blockIdx.x;

    if (b < 1536) {
        // ---------------- prep part ----------------
        if (b < 1024) {   // zero out: 524288 float4 over 1024 blocks
            float4* o4 = (float4*)out;
            int zb = b * 512 + tid;
            o4[zb]       = make_float4(0.f, 0.f, 0.f, 0.f);
            o4[zb + 256] = make_float4(0.f, 0.f, 0.f, 0.f);
        }
        if (b < 512) {
            int e = b >> 5, jc = b & 31;
            for (int i = tid; i < 2048; i += 256) {
                int d = i >> 3, j4 = i & 7;
                *(float4*)&s[d * 36 + j4 * 4] =
                    ((const float4*)(W1 + ((size_t)e * DM + d) * HID + jc * 32))[j4];
            }
            __syncthreads();
            uint2* dst = g_w1h + (size_t)e * 65536 + jc * 2048;
            for (int o = tid; o < 2048; o += 256) {
                int lane = o & 31, nt = (o >> 5) & 3, ks = o >> 7;
                int g = lane >> 2, c = lane & 3;
                int n = nt * 8 + g, k0 = ks * 16 + 2 * c;
                uint2 val;
                val.x = pk(s[k0 * 36 + n],       s[(k0 + 1) * 36 + n]);
                val.y = pk(s[(k0 + 8) * 36 + n], s[(k0 + 9) * 36 + n]);
                dst[o] = val;
            }
        } else {
            int t = b - 512;
            int e = t >> 6, sc = (t >> 2) & 15, ks2 = t & 3;
            for (int i = tid; i < 1024; i += 256) {
                int rl = i >> 6, n4 = i & 63;
                *(float4*)&s[rl * 260 + n4 * 4] =
                    ((const float4*)(W2 + ((size_t)e * HID + sc * 64 + ks2 * 16 + rl) * DM))[n4];
            }
            __syncthreads();
            uint2* dst = g_w2h + (size_t)e * 65536 + sc * 4096 + ks2 * 1024;
            for (int o = tid; o < 1024; o += 256) {
                int lane = o & 31, nt = o >> 5;
                int g = lane >> 2, c = lane & 3;
                int n = nt * 8 + g, k0 = 2 * c;
                uint2 val;
                val.x = pk(s[k0 * 260 + n],       s[(k0 + 1) * 260 + n]);
                val.y = pk(s[(k0 + 8) * 260 + n], s[(k0 + 9) * 260 + n]);
                dst[o] = val;
            }
        }
        return;
    }

    // ---------------- router part (bit-exact fp32 sequence) ----------------
    int rb   = b - 1536;
    int vi   = rb >> 10;
    int bx   = rb & 1023;
    int warp = tid >> 5;
    int lane = tid & 31;
    int tok  = bx * 8 + warp;

    const float* vbase = (vi == 0) ? v0 : ((vi == 1) ? v1 : v2);
    const float* v = vbase + tok * DM;

    float4 a = ((const float4*)v)[lane];
    float4 bb = ((const float4*)v)[lane + 32];

    float vv = wredsum(d4(a, a) + d4(bb, bb));

    const float* rwv = rw + (size_t)vi * NE * DM;
    float lg[NE];
#pragma unroll
    for (int e = 0; e < NE; e++) {
        const float4* kp = (const float4*)(keys + e * DM);
        const float4* rp = (const float4*)(rwv + e * DM);
        float4 k1 = kp[lane], k2 = kp[lane + 32];
        float4 r1 = rp[lane], r2 = rp[lane + 32];
        float dk = wredsum(d4(a, k1) + d4(bb, k2));
        float dr = wredsum(d4(a, r1) + d4(bb, r2));
        float kk = wredsum(d4(k1, k1) + d4(k2, k2));
        float sq = (vv + kk) - 2.0f * dk;
        lg[e] = (-sq) + dr;
    }

    if (lane == 0) {
        unsigned chosen = 0;
        float tv[TOPK];
        int   ti[TOPK];
#pragma unroll
        for (int k = 0; k < TOPK; k++) {
            float m = -1e30f; int mi = 0;
#pragma unroll
            for (int e = 0; e < NE; e++) {
                if (!((chosen >> e) & 1u) && lg[e] > m) { m = lg[e]; mi = e; }
            }
            tv[k] = m; ti[k] = mi; chosen |= (1u << mi);
        }
        float sum = 0.f;
        float ex[TOPK];
#pragma unroll
        for (int k = 0; k < TOPK; k++) { ex[k] = expf(tv[k] - tv[0]); sum += ex[k]; }
        float inv = 1.0f / sum;
#pragma unroll
        for (int k = 0; k < TOPK; k++) {
            int ge  = vi * NE + ti[k];
            int pos = atomicAdd(&g_cnt[ge], 1);
            g_tok [ge * N_TOK + pos] = tok;
            g_gate[ge * N_TOK + pos] = ex[k] * inv;
        }
    }
}

// ---- kernel 1: grouped FFN on fp16 mma, m32n32 GEMM1 tiles, 8 barriers -----
extern "C" __global__ void __launch_bounds__(256, 2)
ffn_kernel(const float* __restrict__ v0, const float* __restrict__ v1,
           const float* __restrict__ v2,
           const float* __restrict__ b1, const float* __restrict__ b2,
           float* __restrict__ out) {
    extern __shared__ float sm[];
    uint32_t* smu = (uint32_t*)sm;
    int tid = threadIdx.x, wid = tid >> 5, lane = tid & 31;
    int vi = blockIdx.z, e = blockIdx.y, g0 = vi * NE + e;
    int cnt = g_cnt[g0];
    int t0 = blockIdx.x * TM;
    if (t0 >= cnt) return;
    int rows = min(TM, cnt - t0);

    int*   s_tok  = (int*)&sm[TOK_F];
    float* s_gate = &sm[GATE_F];
    if (tid < TM) {
        int idx = t0 + tid;
        s_tok [tid] = (idx < cnt) ? g_tok [g0 * N_TOK + idx] : 0;
        s_gate[tid] = (idx < cnt) ? g_gate[g0 * N_TOK + idx] : 0.0f;
    }
    for (int i = tid; i < HID; i += 256) sm[B1_F + i] = b1[(size_t)e * HID + i];
    for (int i = tid; i < DM;  i += 256) sm[B2_F + i] = b2[(size_t)e * DM + i];
    __syncthreads();

    const float* V = (vi == 0) ? v0 : ((vi == 1) ? v1 : v2);

    // ---- gather X -> fp16 A-frag smem ----
    for (int i = tid; i < TM * 64; i += 256) {
        int r = i >> 6, c4 = i & 63;
        float4 v = make_float4(0.f, 0.f, 0.f, 0.f);
        if (r < rows) v = ((const float4*)(V + (size_t)s_tok[r] * DM))[c4];
        uint32_t h01 = pk(v.x, v.y), h23 = pk(v.z, v.w);
        int mt = r >> 4, p = (r >> 3) & 1, g = r & 7;
        int c2 = 2 * c4, ks = c2 >> 3, c2in = c2 & 7;
        int q = p + 2 * (c2in >> 2), ca = c2in & 3;
        int base = ((mt * 16 + ks) * 32 + g * 4 + ca) * 4 + q;
        smu[XP_U + base]     = h01;
        smu[XP_U + base + 4] = h23;
    }
    __syncthreads();

    const uint4* XP  = (const uint4*)&smu[XP_U];
    const uint2* W1B = g_w1h + (size_t)e * 65536;
    const uint2* W2B = g_w2h + (size_t)e * 65536;
    const int gg = lane >> 2, cc = lane & 3;
    const int m1 = wid & 1, ch = wid >> 1;   // GEMM1: m-half, chunk (0..3)
    const int nb = wid * 4;                  // GEMM2 n-octet base

    float4 acc[4][4];   // GEMM2: warp tile m64 x n32
#pragma unroll
    for (int i = 0; i < 4; i++)
#pragma unroll
        for (int j = 0; j < 4; j++) acc[i][j] = make_float4(0.f, 0.f, 0.f, 0.f);

#pragma unroll 1
    for (int sc = 0; sc < 8; sc++) {       // superchunk = 128 cols of HID
        // ===== GEMM1: chunk jc = sc*4+ch, warp tile m32 x n32, K=256 ========
        int jc = sc * 4 + ch;
        float4 a1[2][4];
#pragma unroll
        for (int i = 0; i < 2; i++)
#pragma unroll
            for (int j = 0; j < 4; j++) a1[i][j] = make_float4(0.f, 0.f, 0.f, 0.f);
        {
            const uint2* W1j = W1B + jc * 2048 + lane;
            uint2 bb[2][4];
#pragma unroll
            for (int nt = 0; nt < 4; nt++) {
                bb[0][nt] = W1j[nt * 32];
                bb[1][nt] = W1j[(4 + nt) * 32];
            }
#pragma unroll
            for (int ks = 0; ks < 16; ks++) {
                uint2 bc[4];
#pragma unroll
                for (int nt = 0; nt < 4; nt++) bc[nt] = bb[ks & 1][nt];
                if (ks + 2 < 16) {
#pragma unroll
                    for (int nt = 0; nt < 4; nt++)
                        bb[ks & 1][nt] = W1j[((ks + 2) * 4 + nt) * 32];
                }
#pragma unroll
                for (int mt2 = 0; mt2 < 2; mt2++) {
                    uint4 a = XP[((2 * m1 + mt2) * 16 + ks) * 32 + lane];
#pragma unroll
                    for (int nt = 0; nt < 4; nt++)
                        mma16(a1[mt2][nt], a, bc[nt].x, bc[nt].y);
                }
            }
        }

        // ---- bias + exact GELU -> H[sc&1] fp16 A-frag ----
        // Safe without pre-write barrier: any warp still reading this buffer
        // would be in GEMM2(sc-2), impossible past BAR(sc-1).
        uint32_t* HB = &smu[HP_U + (sc & 1) * 4096];
#pragma unroll
        for (int mt2 = 0; mt2 < 2; mt2++) {
            int mt = 2 * m1 + mt2;
#pragma unroll
            for (int nt = 0; nt < 4; nt++) {
                int ks2 = 2 * ch + (nt >> 1);   // k16 index within superchunk
                int tt  = nt & 1;
                int c0 = jc * 32 + nt * 8 + 2 * cc;
                float bx = sm[B1_F + c0];
                float by = sm[B1_F + c0 + 1];
                float4 v = a1[mt2][nt];
                int rowbase = ((mt * 8 + ks2) * 32 + gg * 4 + cc) * 4;
                uint2 hv;
                hv.x = pk(gelu_exact(v.x + bx), gelu_exact(v.y + by)); // rows g
                hv.y = pk(gelu_exact(v.z + bx), gelu_exact(v.w + by)); // rows g+8
                *(uint2*)&HB[rowbase + 2 * tt] = hv;
            }
        }
        __syncthreads();   // single barrier per stage: H[sc&1] ready

        // ===== GEMM2: warp tile m64 x n32, K = 128 (8 k16-steps) ============
        {
            const uint4* HPq = (const uint4*)HB;
            const uint2* W2s = W2B + (2 * sc) * 4096;
            uint2 wb[2][4];
#pragma unroll
            for (int nt = 0; nt < 4; nt++) {
                wb[0][nt] = W2s[(nb + nt) * 32 + lane];
                wb[1][nt] = W2s[1024 + (nb + nt) * 32 + lane];
            }
#pragma unroll
            for (int ks2 = 0; ks2 < 8; ks2++) {
                uint2 bc[4];
#pragma unroll
                for (int nt = 0; nt < 4; nt++) bc[nt] = wb[ks2 & 1][nt];
                if (ks2 + 2 < 8) {
                    int kq = ks2 + 2;
                    const uint2* Wn = W2s + (kq >> 2) * 4096 + (kq & 3) * 1024;
#pragma unroll
                    for (int nt = 0; nt < 4; nt++)
                        wb[ks2 & 1][nt] = Wn[(nb + nt) * 32 + lane];
                }
#pragma unroll
                for (int mt = 0; mt < 4; mt++) {
                    uint4 h = HPq[(mt * 8 + ks2) * 32 + lane];
#pragma unroll
                    for (int nt = 0; nt < 4; nt++)
                        mma16(acc[mt][nt], h, bc[nt].x, bc[nt].y);
                }
            }
        }
    }

    // ---- epilogue: out[tok,:] += gate * (acc + b2), vector red ----
#pragma unroll
    for (int nt = 0; nt < 4; nt++) {
        int col = (nb + nt) * 8 + 2 * cc;
        float b2a = sm[B2_F + col], b2b = sm[B2_F + col + 1];
#pragma unroll
        for (int mt = 0; mt < 4; mt++) {
            float4 f = acc[mt][nt];
            int ra = mt * 16 + gg;
            int rb = ra + 8;
            if (ra < rows) {
                float gt = s_gate[ra];
                red2(out + (size_t)s_tok[ra] * DM + col,
                     gt * (f.x + b2a), gt * (f.y + b2b));
            }
            if (rb < rows) {
                float gt = s_gate[rb];
                red2(out + (size_t)s_tok[rb] * DM + col,
                     gt * (f.z + b2a), gt * (f.w + b2b));
            }
        }
    }
}

// ---------------- launch ----------------
extern "C" void kernel_launch(void* const* d_in, const int* in_sizes, int n_in,
                              void* d_out, int out_size) {
    const float* v0   = (const float*)d_in[0];
    const float* v1   = (const float*)d_in[1];
    const float* v2   = (const float*)d_in[2];
    const float* rw   = (const float*)d_in[3];
    const float* keys = (const float*)d_in[4];
    const float* W1   = (const float*)d_in[5];
    const float* b1   = (const float*)d_in[6];
    const float* W2   = (const float*)d_in[7];
    const float* b2   = (const float*)d_in[8];
    float* out = (float*)d_out;

    static void* cnt_addr = nullptr;
    if (!cnt_addr) cudaGetSymbolAddress(&cnt_addr, g_cnt);

    cudaFuncSetAttribute(ffn_kernel, cudaFuncAttributeMaxDynamicSharedMemorySize,
                         SMEM_BYTES);

    cudaMemsetAsync(cnt_addr, 0, sizeof(int) * NVIEW * NE, 0);

    prep_router_kernel<<<4608, 256, 0, 0>>>(W1, W2, v0, v1, v2, rw, keys, out);

    dim3 fgrid(N_TOK / TM, NE, NVIEW);   // 128 x 16 x 3, most blocks exit early
    ffn_kernel<<<fgrid, 256, SMEM_BYTES, 0>>>(v0, v1, v2, b1, b2, out);
}

// round 15
// speedup vs baseline: 1.0404x; 1.0404x over previous
#include <cuda_runtime.h>
#include <cuda_fp16.h>
#include <math.h>
#include <cstdint>

#define N_TOK   8192
#define DM      256
#define NE      16
#define NVIEW   3
#define TOPK    4
#define HID     1024
#define TM      64
#define NGRP    (NVIEW * NE)
#define NBLK    296          // 148 SMs x 2 resident blocks

// ---- ffn smem layout (32-bit word indices) ----
#define XP_U    0           // X fp16 A-frag: [4mt][16ks][32lane][4] uints = 8192
#define HP_U    8192        // H fp16 A-frag QUAD buffer: 4 x 2048 uints = 8192
#define B1_F    16384       // 1024 floats
#define B2_F    17408       // 256
#define TOK_F   17664       // 64 ints
#define GATE_F  17728       // 64
#define CNT_F   17792       // 48 ints (cached g_cnt)
#define WI_F    17840       // 1 int (claimed work item)
#define SMEM_WORDS 17844
#define SMEM_BYTES (SMEM_WORDS * 4)    // 71376 -> 2 blocks/SM

// ---------------- device scratch ----------------
__device__ int   g_cnt [64];           // [0..47] counts, [63] work ticket
__device__ int   g_tok [NGRP * N_TOK];
__device__ float g_gate[NGRP * N_TOK];
__device__ uint2 g_w1h [NE * 65536];   // W1 fp16 B-frag order, 8 MB
__device__ uint2 g_w2h [NE * 65536];   // W2 fp16 B-frag order, 8 MB

// ---------------- helpers ----------------
__device__ __forceinline__ uint32_t pk(float lo, float hi) {
    __half2 h = __floats2half2_rn(lo, hi);   // .x = lo (low 16 bits)
    return *reinterpret_cast<uint32_t*>(&h);
}
__device__ __forceinline__ float d4(float4 a, float4 b) {
    return a.x * b.x + a.y * b.y + a.z * b.z + a.w * b.w;
}
__device__ __forceinline__ float wredsum(float x) {
#pragma unroll
    for (int o = 16; o > 0; o >>= 1) x += __shfl_xor_sync(0xffffffffu, x, o);
    return x;
}
__device__ __forceinline__ float gelu_exact(float x) {
    return 0.5f * x * (1.0f + erff(x * 0.70710678118654752440f));
}
// m16n8k16 fp16 mma, fp32 accumulate: D += A*B
__device__ __forceinline__ void mma16(float4& d, const uint4& a,
                                      uint32_t b0, uint32_t b1) {
    asm volatile(
        "mma.sync.aligned.m16n8k16.row.col.f32.f16.f16.f32 "
        "{%0,%1,%2,%3}, {%4,%5,%6,%7}, {%8,%9}, {%0,%1,%2,%3};"
        : "+f"(d.x), "+f"(d.y), "+f"(d.z), "+f"(d.w)
        : "r"(a.x), "r"(a.y), "r"(a.z), "r"(a.w), "r"(b0), "r"(b1));
}
__device__ __forceinline__ void red2(float* p, float a, float b) {
    asm volatile("red.global.add.v2.f32 [%0], {%1, %2};"
                 :: "l"(p), "f"(a), "f"(b) : "memory");
}

// ---- merged kernel 0: prep (blocks 0..1535) + router (blocks 1536..4607) ---
// g_cnt (incl. ticket) must be zeroed by a prior memset (in kernel_launch).
__global__ void prep_router_kernel(const float* __restrict__ W1,
                                   const float* __restrict__ W2,
                                   const float* __restrict__ v0,
                                   const float* __restrict__ v1,
                                   const float* __restrict__ v2,
                                   const float* __restrict__ rw,
                                   const float* __restrict__ keys,
                                   float* __restrict__ out) {
    __shared__ float s[9216];
    int tid = threadIdx.x, b = blockIdx.x;

    if (b < 1536) {
        // ---------------- prep part ----------------
        if (b < 1024) {   // zero out: 524288 float4 over 1024 blocks
            float4* o4 = (float4*)out;
            int zb = b * 512 + tid;
            o4[zb]       = make_float4(0.f, 0.f, 0.f, 0.f);
            o4[zb + 256] = make_float4(0.f, 0.f, 0.f, 0.f);
        }
        if (b < 512) {
            int e = b >> 5, jc = b & 31;
            for (int i = tid; i < 2048; i += 256) {
                int d = i >> 3, j4 = i & 7;
                *(float4*)&s[d * 36 + j4 * 4] =
                    ((const float4*)(W1 + ((size_t)e * DM + d) * HID + jc * 32))[j4];
            }
            __syncthreads();
            uint2* dst = g_w1h + (size_t)e * 65536 + jc * 2048;
            for (int o = tid; o < 2048; o += 256) {
                int lane = o & 31, nt = (o >> 5) & 3, ks = o >> 7;
                int g = lane >> 2, c = lane & 3;
                int n = nt * 8 + g, k0 = ks * 16 + 2 * c;
                uint2 val;
                val.x = pk(s[k0 * 36 + n],       s[(k0 + 1) * 36 + n]);
                val.y = pk(s[(k0 + 8) * 36 + n], s[(k0 + 9) * 36 + n]);
                dst[o] = val;
            }
        } else {
            int t = b - 512;
            int e = t >> 6, sc = (t >> 2) & 15, ks2 = t & 3;
            for (int i = tid; i < 1024; i += 256) {
                int rl = i >> 6, n4 = i & 63;
                *(float4*)&s[rl * 260 + n4 * 4] =
                    ((const float4*)(W2 + ((size_t)e * HID + sc * 64 + ks2 * 16 + rl) * DM))[n4];
            }
            __syncthreads();
            uint2* dst = g_w2h + (size_t)e * 65536 + sc * 4096 + ks2 * 1024;
            for (int o = tid; o < 1024; o += 256) {
                int lane = o & 31, nt = o >> 5;
                int g = lane >> 2, c = lane & 3;
                int n = nt * 8 + g, k0 = 2 * c;
                uint2 val;
                val.x = pk(s[k0 * 260 + n],       s[(k0 + 1) * 260 + n]);
                val.y = pk(s[(k0 + 8) * 260 + n], s[(k0 + 9) * 260 + n]);
                dst[o] = val;
            }
        }
        return;
    }

    // ---------------- router part (bit-exact fp32 sequence) ----------------
    int rb   = b - 1536;
    int vi   = rb >> 10;
    int bx   = rb & 1023;
    int warp = tid >> 5;
    int lane = tid & 31;
    int tok  = bx * 8 + warp;

    const float* vbase = (vi == 0) ? v0 : ((vi == 1) ? v1 : v2);
    const float* v = vbase + tok * DM;

    float4 a = ((const float4*)v)[lane];
    float4 bb = ((const float4*)v)[lane + 32];

    float vv = wredsum(d4(a, a) + d4(bb, bb));

    const float* rwv = rw + (size_t)vi * NE * DM;
    float lg[NE];
#pragma unroll
    for (int e = 0; e < NE; e++) {
        const float4* kp = (const float4*)(keys + e * DM);
        const float4* rp = (const float4*)(rwv + e * DM);
        float4 k1 = kp[lane], k2 = kp[lane + 32];
        float4 r1 = rp[lane], r2 = rp[lane + 32];
        float dk = wredsum(d4(a, k1) + d4(bb, k2));
        float dr = wredsum(d4(a, r1) + d4(bb, r2));
        float kk = wredsum(d4(k1, k1) + d4(k2, k2));
        float sq = (vv + kk) - 2.0f * dk;
        lg[e] = (-sq) + dr;
    }

    if (lane == 0) {
        unsigned chosen = 0;
        float tv[TOPK];
        int   ti[TOPK];
#pragma unroll
        for (int k = 0; k < TOPK; k++) {
            float m = -1e30f; int mi = 0;
#pragma unroll
            for (int e = 0; e < NE; e++) {
                if (!((chosen >> e) & 1u) && lg[e] > m) { m = lg[e]; mi = e; }
            }
            tv[k] = m; ti[k] = mi; chosen |= (1u << mi);
        }
        float sum = 0.f;
        float ex[TOPK];
#pragma unroll
        for (int k = 0; k < TOPK; k++) { ex[k] = expf(tv[k] - tv[0]); sum += ex[k]; }
        float inv = 1.0f / sum;
#pragma unroll
        for (int k = 0; k < TOPK; k++) {
            int ge  = vi * NE + ti[k];
            int pos = atomicAdd(&g_cnt[ge], 1);
            g_tok [ge * N_TOK + pos] = tok;
            g_gate[ge * N_TOK + pos] = ex[k] * inv;
        }
    }
}

// ---- GEMM2 inner step: acc += H(stage) @ W2(stage), K=64 -------------------
__device__ __forceinline__ void gemm2_step(float4 (&acc)[4][4],
                                           const uint4* HPq, const uint2* W2s,
                                           uint2 (&wb)[2][4],
                                           int nb, int lane, bool preloaded) {
    if (!preloaded) {
#pragma unroll
        for (int nt = 0; nt < 4; nt++) {
            wb[0][nt] = W2s[(nb + nt) * 32 + lane];
            wb[1][nt] = W2s[(32 + nb + nt) * 32 + lane];
        }
    }
#pragma unroll
    for (int ks2 = 0; ks2 < 4; ks2++) {
        uint2 bc[4];
#pragma unroll
        for (int nt = 0; nt < 4; nt++) bc[nt] = wb[ks2 & 1][nt];
        if (ks2 + 2 < 4) {
#pragma unroll
            for (int nt = 0; nt < 4; nt++)
                wb[ks2 & 1][nt] = W2s[((ks2 + 2) * 32 + nb + nt) * 32 + lane];
        }
#pragma unroll
        for (int mt = 0; mt < 4; mt++) {
            uint4 h = HPq[(mt * 4 + ks2) * 32 + lane];
#pragma unroll
            for (int nt = 0; nt < 4; nt++)
                mma16(acc[mt][nt], h, bc[nt].x, bc[nt].y);
        }
    }
}

// ---- kernel 1: persistent grouped FFN, work-stealing over (group, tile) ----
extern "C" __global__ void __launch_bounds__(256, 2)
ffn_kernel(const float* __restrict__ v0, const float* __restrict__ v1,
           const float* __restrict__ v2,
           const float* __restrict__ b1, const float* __restrict__ b2,
           float* __restrict__ out) {
    extern __shared__ float sm[];
    uint32_t* smu = (uint32_t*)sm;
    int tid = threadIdx.x, wid = tid >> 5, lane = tid & 31;

    int*   s_tok  = (int*)&sm[TOK_F];
    float* s_gate = &sm[GATE_F];
    int*   s_cnt  = (int*)&sm[CNT_F];
    int*   s_wi   = (int*)&sm[WI_F];

    if (tid < NGRP) s_cnt[tid] = g_cnt[tid];

    const int gg = lane >> 2, cc = lane & 3;
    const int m1 = wid & 1, n1 = (wid >> 1) & 1, ch = wid >> 2;   // GEMM1 roles
    const int nb = wid * 4;                                       // GEMM2 role

    for (;;) {
        if (tid == 0) s_wi[0] = atomicAdd(&g_cnt[63], 1);
        __syncthreads();   // claim visible; also fences previous item's smem use
        int wi = s_wi[0];

        // map work item -> (group, tile)
        int my_g = -1, my_t = 0, acc0 = 0;
#pragma unroll 1
        for (int g = 0; g < NGRP; g++) {
            int nt = (s_cnt[g] + TM - 1) / TM;
            if (my_g < 0 && wi < acc0 + nt) { my_g = g; my_t = wi - acc0; }
            acc0 += nt;
        }
        if (my_g < 0) break;

        int vi = my_g >> 4, e = my_g & 15;
        int cnt = s_cnt[my_g];
        int t0 = my_t * TM;
        int rows = min(TM, cnt - t0);

        if (tid < TM) {
            int idx = t0 + tid;
            s_tok [tid] = (idx < cnt) ? g_tok [my_g * N_TOK + idx] : 0;
            s_gate[tid] = (idx < cnt) ? g_gate[my_g * N_TOK + idx] : 0.0f;
        }
        for (int i = tid; i < HID; i += 256) sm[B1_F + i] = b1[(size_t)e * HID + i];
        for (int i = tid; i < DM;  i += 256) sm[B2_F + i] = b2[(size_t)e * DM + i];
        __syncthreads();

        const float* V = (vi == 0) ? v0 : ((vi == 1) ? v1 : v2);

        // ---- gather X -> fp16 A-frag smem ----
        for (int i = tid; i < TM * 64; i += 256) {
            int r = i >> 6, c4 = i & 63;
            float4 v = make_float4(0.f, 0.f, 0.f, 0.f);
            if (r < rows) v = ((const float4*)(V + (size_t)s_tok[r] * DM))[c4];
            uint32_t h01 = pk(v.x, v.y), h23 = pk(v.z, v.w);
            int mt = r >> 4, p = (r >> 3) & 1, g = r & 7;
            int c2 = 2 * c4, ks = c2 >> 3, c2in = c2 & 7;
            int q = p + 2 * (c2in >> 2), ca = c2in & 3;
            int base = ((mt * 16 + ks) * 32 + g * 4 + ca) * 4 + q;
            smu[XP_U + base]     = h01;
            smu[XP_U + base + 4] = h23;
        }
        __syncthreads();

        const uint4* XP  = (const uint4*)&smu[XP_U];
        const uint2* W1B = g_w1h + (size_t)e * 65536;
        const uint2* W2B = g_w2h + (size_t)e * 65536;

        float4 acc[4][4];   // GEMM2: warp tile m64 x n32
#pragma unroll
        for (int i = 0; i < 4; i++)
#pragma unroll
            for (int j = 0; j < 4; j++) acc[i][j] = make_float4(0.f, 0.f, 0.f, 0.f);

#pragma unroll 1
        for (int t = 0; t < 8; t++) {
            // ===== two superchunks of GEMM1 + GELU into quad-buffered H =====
#pragma unroll
            for (int h2 = 0; h2 < 2; h2++) {
                int sc = 2 * t + h2;
                int jc = sc * 2 + ch;
                float4 a1[2][2];
#pragma unroll
                for (int i = 0; i < 2; i++)
#pragma unroll
                    for (int j = 0; j < 2; j++) a1[i][j] = make_float4(0.f, 0.f, 0.f, 0.f);
                {
                    const uint2* W1j = W1B + jc * 2048 + lane;
                    const int nt0 = 2 * n1, nt1 = nt0 + 1;
                    uint2 bb[2][2];
                    bb[0][0] = W1j[nt0 * 32];        bb[0][1] = W1j[nt1 * 32];
                    bb[1][0] = W1j[(4 + nt0) * 32];  bb[1][1] = W1j[(4 + nt1) * 32];
#pragma unroll
                    for (int ks = 0; ks < 16; ks++) {
                        uint2 bc0 = bb[ks & 1][0], bc1 = bb[ks & 1][1];
                        if (ks + 2 < 16) {
                            bb[ks & 1][0] = W1j[((ks + 2) * 4 + nt0) * 32];
                            bb[ks & 1][1] = W1j[((ks + 2) * 4 + nt1) * 32];
                        }
#pragma unroll
                        for (int mt2 = 0; mt2 < 2; mt2++) {
                            int mt = 2 * m1 + mt2;
                            uint4 a = XP[(mt * 16 + ks) * 32 + lane];
                            mma16(a1[mt2][0], a, bc0.x, bc0.y);
                            mma16(a1[mt2][1], a, bc1.x, bc1.y);
                        }
                    }
                }
                // bias + exact GELU -> H[sc&3]. Safe without barrier: stage
                // t-1's GEMM2 read buffers {2t+2,2t+3} mod 4, disjoint.
                uint32_t* HB = &smu[HP_U + (sc & 3) * 2048];
                int ks2 = 2 * ch + n1;
#pragma unroll
                for (int mt2 = 0; mt2 < 2; mt2++) {
                    int mt = 2 * m1 + mt2;
                    int rowbase = ((mt * 4 + ks2) * 32 + gg * 4 + cc) * 4;
#pragma unroll
                    for (int tt = 0; tt < 2; tt++) {
                        int nt = 2 * n1 + tt;
                        int c0 = jc * 32 + nt * 8 + 2 * cc;
                        float bx = sm[B1_F + c0];
                        float by = sm[B1_F + c0 + 1];
                        float4 v = a1[mt2][tt];
                        uint2 hv;
                        hv.x = pk(gelu_exact(v.x + bx), gelu_exact(v.y + by));
                        hv.y = pk(gelu_exact(v.z + bx), gelu_exact(v.w + by));
                        *(uint2*)&HB[rowbase + 2 * tt] = hv;
                    }
                }
            }

            // hoist W2 fragments for superchunk 2t (hides L2 over barrier)
            const uint2* W2s0 = W2B + (2 * t) * 4096;
            uint2 wb[2][4];
#pragma unroll
            for (int nt = 0; nt < 4; nt++) {
                wb[0][nt] = W2s0[(nb + nt) * 32 + lane];
                wb[1][nt] = W2s0[(32 + nb + nt) * 32 + lane];
            }
            __syncthreads();   // single barrier per stage: H buffers ready

            // ===== two superchunks of GEMM2 (sc ascending) ==================
            gemm2_step(acc, (const uint4*)&smu[HP_U + ((2 * t) & 3) * 2048],
                       W2s0, wb, nb, lane, true);
            gemm2_step(acc, (const uint4*)&smu[HP_U + ((2 * t + 1) & 3) * 2048],
                       W2B + (2 * t + 1) * 4096, wb, nb, lane, false);
        }

        // ---- epilogue: out[tok,:] += gate * (acc + b2), vector red ----
#pragma unroll
        for (int nt = 0; nt < 4; nt++) {
            int col = (nb + nt) * 8 + 2 * cc;
            float b2a = sm[B2_F + col], b2b = sm[B2_F + col + 1];
#pragma unroll
            for (int mt = 0; mt < 4; mt++) {
                float4 f = acc[mt][nt];
                int ra = mt * 16 + gg;
                int rb2 = ra + 8;
                if (ra < rows) {
                    float gt = s_gate[ra];
                    red2(out + (size_t)s_tok[ra] * DM + col,
                         gt * (f.x + b2a), gt * (f.y + b2b));
                }
                if (rb2 < rows) {
                    float gt = s_gate[rb2];
                    red2(out + (size_t)s_tok[rb2] * DM + col,
                         gt * (f.z + b2a), gt * (f.w + b2b));
                }
            }
        }
        // loop back: claim barrier at top fences smem reuse
    }
}

// ---------------- launch ----------------
extern "C" void kernel_launch(void* const* d_in, const int* in_sizes, int n_in,
                              void* d_out, int out_size) {
    const float* v0   = (const float*)d_in[0];
    const float* v1   = (const float*)d_in[1];
    const float* v2   = (const float*)d_in[2];
    const float* rw   = (const float*)d_in[3];
    const float* keys = (const float*)d_in[4];
    const float* W1   = (const float*)d_in[5];
    const float* b1   = (const float*)d_in[6];
    const float* W2   = (const float*)d_in[7];
    const float* b2   = (const float*)d_in[8];
    float* out = (float*)d_out;

    static void* cnt_addr = nullptr;
    if (!cnt_addr) cudaGetSymbolAddress(&cnt_addr, g_cnt);

    cudaFuncSetAttribute(ffn_kernel, cudaFuncAttributeMaxDynamicSharedMemorySize,
                         SMEM_BYTES);

    cudaMemsetAsync(cnt_addr, 0, sizeof(int) * 64, 0);

    prep_router_kernel<<<4608, 256, 0, 0>>>(W1, W2, v0, v1, v2, rw, keys, out);

    ffn_kernel<<<NBLK, 256, SMEM_BYTES, 0>>>(v0, v1, v2, b1, b2, out);
}

// round 16
// speedup vs baseline: 1.0545x; 1.0136x over previous
#include <cuda_runtime.h>
#include <cuda_fp16.h>
#include <math.h>
#include <cstdint>

#define N_TOK   8192
#define DM      256
#define NE      16
#define NVIEW   3
#define TOPK    4
#define HID     1024
#define TM      64

// ---- ffn smem layout (32-bit word indices) ----
#define XP_U    0           // X fp16 A-frag: [4mt][16ks][32lane][4] uints = 8192
#define HP_U    8192        // H fp16 A-frag QUAD buffer: 4 x 2048 uints = 8192
#define B1_F    16384       // 1024 floats
#define B2_F    17408       // 256
#define TOK_F   17664       // 64 ints
#define GATE_F  17728       // 64
#define SMEM_WORDS 17792
#define SMEM_BYTES (SMEM_WORDS * 4)    // 71168 -> 2 blocks/SM

// ---------------- device scratch ----------------
__device__ int   g_cnt [NVIEW * NE];
__device__ int   g_tok [NVIEW * NE * N_TOK];
__device__ float g_gate[NVIEW * NE * N_TOK];
__device__ uint2 g_w1h [NE * 65536];   // W1 fp16 B-frag order, 8 MB
__device__ uint2 g_w2h [NE * 65536];   // W2 fp16 B-frag order, 8 MB

// ---------------- helpers ----------------
__device__ __forceinline__ uint32_t pk(float lo, float hi) {
    __half2 h = __floats2half2_rn(lo, hi);   // .x = lo (low 16 bits)
    return *reinterpret_cast<uint32_t*>(&h);
}
__device__ __forceinline__ float d4(float4 a, float4 b) {
    return a.x * b.x + a.y * b.y + a.z * b.z + a.w * b.w;
}
__device__ __forceinline__ float wredsum(float x) {
#pragma unroll
    for (int o = 16; o > 0; o >>= 1) x += __shfl_xor_sync(0xffffffffu, x, o);
    return x;
}
__device__ __forceinline__ float gelu_exact(float x) {
    return 0.5f * x * (1.0f + erff(x * 0.70710678118654752440f));
}
// m16n8k16 fp16 mma, fp32 accumulate: D += A*B
__device__ __forceinline__ void mma16(float4& d, const uint4& a,
                                      uint32_t b0, uint32_t b1) {
    asm volatile(
        "mma.sync.aligned.m16n8k16.row.col.f32.f16.f16.f32 "
        "{%0,%1,%2,%3}, {%4,%5,%6,%7}, {%8,%9}, {%0,%1,%2,%3};"
        : "+f"(d.x), "+f"(d.y), "+f"(d.z), "+f"(d.w)
        : "r"(a.x), "r"(a.y), "r"(a.z), "r"(a.w), "r"(b0), "r"(b1));
}
__device__ __forceinline__ void red2(float* p, float a, float b) {
    asm volatile("red.global.add.v2.f32 [%0], {%1, %2};"
                 :: "l"(p), "f"(a), "f"(b) : "memory");
}

// ---- merged kernel 0: prep (blocks 0..1535) + router (blocks 1536..4607) ---
// g_cnt must be zeroed by a prior memset (done in kernel_launch).
__global__ void prep_router_kernel(const float* __restrict__ W1,
                                   const float* __restrict__ W2,
                                   const float* __restrict__ v0,
                                   const float* __restrict__ v1,
                                   const float* __restrict__ v2,
                                   const float* __restrict__ rw,
                                   const float* __restrict__ keys,
                                   float* __restrict__ out) {
    __shared__ float s[9216];
    int tid = threadIdx.x, b = blockIdx.x;

    if (b < 1536) {
        // ---------------- prep part ----------------
        if (b < 1024) {   // zero out: 524288 float4 over 1024 blocks
            float4* o4 = (float4*)out;
            int zb = b * 512 + tid;
            o4[zb]       = make_float4(0.f, 0.f, 0.f, 0.f);
            o4[zb + 256] = make_float4(0.f, 0.f, 0.f, 0.f);
        }
        if (b < 512) {
            int e = b >> 5, jc = b & 31;
            for (int i = tid; i < 2048; i += 256) {
                int d = i >> 3, j4 = i & 7;
                *(float4*)&s[d * 36 + j4 * 4] =
                    ((const float4*)(W1 + ((size_t)e * DM + d) * HID + jc * 32))[j4];
            }
            __syncthreads();
            uint2* dst = g_w1h + (size_t)e * 65536 + jc * 2048;
            for (int o = tid; o < 2048; o += 256) {
                int lane = o & 31, nt = (o >> 5) & 3, ks = o >> 7;
                int g = lane >> 2, c = lane & 3;
                int n = nt * 8 + g, k0 = ks * 16 + 2 * c;
                uint2 val;
                val.x = pk(s[k0 * 36 + n],       s[(k0 + 1) * 36 + n]);
                val.y = pk(s[(k0 + 8) * 36 + n], s[(k0 + 9) * 36 + n]);
                dst[o] = val;
            }
        } else {
            int t = b - 512;
            int e = t >> 6, sc = (t >> 2) & 15, ks2 = t & 3;
            for (int i = tid; i < 1024; i += 256) {
                int rl = i >> 6, n4 = i & 63;
                *(float4*)&s[rl * 260 + n4 * 4] =
                    ((const float4*)(W2 + ((size_t)e * HID + sc * 64 + ks2 * 16 + rl) * DM))[n4];
            }
            __syncthreads();
            uint2* dst = g_w2h + (size_t)e * 65536 + sc * 4096 + ks2 * 1024;
            for (int o = tid; o < 1024; o += 256) {
                int lane = o & 31, nt = o >> 5;
                int g = lane >> 2, c = lane & 3;
                int n = nt * 8 + g, k0 = 2 * c;
                uint2 val;
                val.x = pk(s[k0 * 260 + n],       s[(k0 + 1) * 260 + n]);
                val.y = pk(s[(k0 + 8) * 260 + n], s[(k0 + 9) * 260 + n]);
                dst[o] = val;
            }
        }
        return;
    }

    // ---------------- router part (bit-exact fp32 sequence) ----------------
    int rb   = b - 1536;
    int vi   = rb >> 10;
    int bx   = rb & 1023;
    int warp = tid >> 5;
    int lane = tid & 31;
    int tok  = bx * 8 + warp;

    const float* vbase = (vi == 0) ? v0 : ((vi == 1) ? v1 : v2);
    const float* v = vbase + tok * DM;

    float4 a = ((const float4*)v)[lane];
    float4 bb = ((const float4*)v)[lane + 32];

    float vv = wredsum(d4(a, a) + d4(bb, bb));

    const float* rwv = rw + (size_t)vi * NE * DM;
    float lg[NE];
#pragma unroll
    for (int e = 0; e < NE; e++) {
        const float4* kp = (const float4*)(keys + e * DM);
        const float4* rp = (const float4*)(rwv + e * DM);
        float4 k1 = kp[lane], k2 = kp[lane + 32];
        float4 r1 = rp[lane], r2 = rp[lane + 32];
        float dk = wredsum(d4(a, k1) + d4(bb, k2));
        float dr = wredsum(d4(a, r1) + d4(bb, r2));
        float kk = wredsum(d4(k1, k1) + d4(k2, k2));
        float sq = (vv + kk) - 2.0f * dk;
        lg[e] = (-sq) + dr;
    }

    if (lane == 0) {
        unsigned chosen = 0;
        float tv[TOPK];
        int   ti[TOPK];
#pragma unroll
        for (int k = 0; k < TOPK; k++) {
            float m = -1e30f; int mi = 0;
#pragma unroll
            for (int e = 0; e < NE; e++) {
                if (!((chosen >> e) & 1u) && lg[e] > m) { m = lg[e]; mi = e; }
            }
            tv[k] = m; ti[k] = mi; chosen |= (1u << mi);
        }
        float sum = 0.f;
        float ex[TOPK];
#pragma unroll
        for (int k = 0; k < TOPK; k++) { ex[k] = expf(tv[k] - tv[0]); sum += ex[k]; }
        float inv = 1.0f / sum;
#pragma unroll
        for (int k = 0; k < TOPK; k++) {
            int ge  = vi * NE + ti[k];
            int pos = atomicAdd(&g_cnt[ge], 1);
            g_tok [ge * N_TOK + pos] = tok;
            g_gate[ge * N_TOK + pos] = ex[k] * inv;
        }
    }
}

// ---- GEMM2 inner step: acc += H(stage) @ W2(stage), K=64 -------------------
__device__ __forceinline__ void gemm2_step(float4 (&acc)[4][4],
                                           const uint4* HPq, const uint2* W2s,
                                           uint2 (&wb)[2][4],
                                           int nb, int lane, bool preloaded) {
    if (!preloaded) {
#pragma unroll
        for (int nt = 0; nt < 4; nt++) {
            wb[0][nt] = W2s[(nb + nt) * 32 + lane];
            wb[1][nt] = W2s[(32 + nb + nt) * 32 + lane];
        }
    }
#pragma unroll
    for (int ks2 = 0; ks2 < 4; ks2++) {
        uint2 bc[4];
#pragma unroll
        for (int nt = 0; nt < 4; nt++) bc[nt] = wb[ks2 & 1][nt];
        if (ks2 + 2 < 4) {
#pragma unroll
            for (int nt = 0; nt < 4; nt++)
                wb[ks2 & 1][nt] = W2s[((ks2 + 2) * 32 + nb + nt) * 32 + lane];
        }
#pragma unroll
        for (int mt = 0; mt < 4; mt++) {
            uint4 h = HPq[(mt * 4 + ks2) * 32 + lane];
#pragma unroll
            for (int nt = 0; nt < 4; nt++)
                mma16(acc[mt][nt], h, bc[nt].x, bc[nt].y);
        }
    }
}

// ---- kernel 1: grouped FFN on fp16 mma, 8 barriers, A-frag double buffer ---
extern "C" __global__ void __launch_bounds__(256, 2)
ffn_kernel(const float* __restrict__ v0, const float* __restrict__ v1,
           const float* __restrict__ v2,
           const float* __restrict__ b1, const float* __restrict__ b2,
           float* __restrict__ out) {
    extern __shared__ float sm[];
    uint32_t* smu = (uint32_t*)sm;
    int tid = threadIdx.x, wid = tid >> 5, lane = tid & 31;
    int vi = blockIdx.z, e = blockIdx.y, g0 = vi * NE + e;
    int cnt = g_cnt[g0];
    int t0 = blockIdx.x * TM;
    if (t0 >= cnt) return;
    int rows = min(TM, cnt - t0);

    int*   s_tok  = (int*)&sm[TOK_F];
    float* s_gate = &sm[GATE_F];
    if (tid < TM) {
        int idx = t0 + tid;
        s_tok [tid] = (idx < cnt) ? g_tok [g0 * N_TOK + idx] : 0;
        s_gate[tid] = (idx < cnt) ? g_gate[g0 * N_TOK + idx] : 0.0f;
    }
    for (int i = tid; i < HID; i += 256) sm[B1_F + i] = b1[(size_t)e * HID + i];
    for (int i = tid; i < DM;  i += 256) sm[B2_F + i] = b2[(size_t)e * DM + i];
    __syncthreads();

    const float* V = (vi == 0) ? v0 : ((vi == 1) ? v1 : v2);

    // ---- gather X -> fp16 A-frag smem ----
    for (int i = tid; i < TM * 64; i += 256) {
        int r = i >> 6, c4 = i & 63;
        float4 v = make_float4(0.f, 0.f, 0.f, 0.f);
        if (r < rows) v = ((const float4*)(V + (size_t)s_tok[r] * DM))[c4];
        uint32_t h01 = pk(v.x, v.y), h23 = pk(v.z, v.w);
        int mt = r >> 4, p = (r >> 3) & 1, g = r & 7;
        int c2 = 2 * c4, ks = c2 >> 3, c2in = c2 & 7;
        int q = p + 2 * (c2in >> 2), ca = c2in & 3;
        int base = ((mt * 16 + ks) * 32 + g * 4 + ca) * 4 + q;
        smu[XP_U + base]     = h01;
        smu[XP_U + base + 4] = h23;
    }
    __syncthreads();

    const uint4* XP  = (const uint4*)&smu[XP_U];
    const uint2* W1B = g_w1h + (size_t)e * 65536;
    const uint2* W2B = g_w2h + (size_t)e * 65536;
    const int gg = lane >> 2, cc = lane & 3;
    const int m1 = wid & 1, n1 = (wid >> 1) & 1, ch = wid >> 2;   // GEMM1 roles
    const int nb = wid * 4;                                       // GEMM2 role

    float4 acc[4][4];   // GEMM2: warp tile m64 x n32
#pragma unroll
    for (int i = 0; i < 4; i++)
#pragma unroll
        for (int j = 0; j < 4; j++) acc[i][j] = make_float4(0.f, 0.f, 0.f, 0.f);

#pragma unroll 1
    for (int t = 0; t < 8; t++) {
        // ===== two superchunks of GEMM1 + GELU into quad-buffered H =========
#pragma unroll
        for (int h2 = 0; h2 < 2; h2++) {
            int sc = 2 * t + h2;
            int jc = sc * 2 + ch;
            float4 a1[2][2];
#pragma unroll
            for (int i = 0; i < 2; i++)
#pragma unroll
                for (int j = 0; j < 2; j++) a1[i][j] = make_float4(0.f, 0.f, 0.f, 0.f);
            {
                const uint2* W1j = W1B + jc * 2048 + lane;
                const int nt0 = 2 * n1, nt1 = nt0 + 1;
                const uint4* xb0 = XP + ((2 * m1) * 16) * 32 + lane;
                const uint4* xb1 = XP + ((2 * m1 + 1) * 16) * 32 + lane;
                uint2 bb[2][2];
                bb[0][0] = W1j[nt0 * 32];        bb[0][1] = W1j[nt1 * 32];
                bb[1][0] = W1j[(4 + nt0) * 32];  bb[1][1] = W1j[(4 + nt1) * 32];
                // A-fragment double buffer (GEMM1-phase registers only)
                uint4 ap0 = xb0[0], ap1 = xb1[0];
#pragma unroll
                for (int ks = 0; ks < 16; ks++) {
                    uint2 bc0 = bb[ks & 1][0], bc1 = bb[ks & 1][1];
                    uint4 ac0 = ap0, ac1 = ap1;
                    if (ks + 1 < 16) {
                        ap0 = xb0[(ks + 1) * 32];
                        ap1 = xb1[(ks + 1) * 32];
                    }
                    if (ks + 2 < 16) {
                        bb[ks & 1][0] = W1j[((ks + 2) * 4 + nt0) * 32];
                        bb[ks & 1][1] = W1j[((ks + 2) * 4 + nt1) * 32];
                    }
                    mma16(a1[0][0], ac0, bc0.x, bc0.y);
                    mma16(a1[0][1], ac0, bc1.x, bc1.y);
                    mma16(a1[1][0], ac1, bc0.x, bc0.y);
                    mma16(a1[1][1], ac1, bc1.x, bc1.y);
                }
            }
            // bias + exact GELU -> H[sc&3]. Safe without barrier: stage t-1's
            // GEMM2 read buffers {2t+2, 2t+3} mod 4, disjoint from {2t, 2t+1}.
            uint32_t* HB = &smu[HP_U + (sc & 3) * 2048];
            int ks2 = 2 * ch + n1;
#pragma unroll
            for (int mt2 = 0; mt2 < 2; mt2++) {
                int mt = 2 * m1 + mt2;
                int rowbase = ((mt * 4 + ks2) * 32 + gg * 4 + cc) * 4;
#pragma unroll
                for (int tt = 0; tt < 2; tt++) {
                    int nt = 2 * n1 + tt;
                    int c0 = jc * 32 + nt * 8 + 2 * cc;
                    float bx = sm[B1_F + c0];
                    float by = sm[B1_F + c0 + 1];
                    float4 v = a1[mt2][tt];
                    uint2 hv;
                    hv.x = pk(gelu_exact(v.x + bx), gelu_exact(v.y + by));
                    hv.y = pk(gelu_exact(v.z + bx), gelu_exact(v.w + by));
                    *(uint2*)&HB[rowbase + 2 * tt] = hv;
                }
            }
        }

        // hoist W2 fragments for superchunk 2t (hides L2 latency over barrier)
        const uint2* W2s0 = W2B + (2 * t) * 4096;
        uint2 wb[2][4];
#pragma unroll
        for (int nt = 0; nt < 4; nt++) {
            wb[0][nt] = W2s0[(nb + nt) * 32 + lane];
            wb[1][nt] = W2s0[(32 + nb + nt) * 32 + lane];
        }
        __syncthreads();   // single barrier per stage: H[2t&3], H[(2t+1)&3] ready

        // ===== two superchunks of GEMM2 (sc ascending: bitwise-same acc) ====
        gemm2_step(acc, (const uint4*)&smu[HP_U + ((2 * t) & 3) * 2048],
                   W2s0, wb, nb, lane, true);
        gemm2_step(acc, (const uint4*)&smu[HP_U + ((2 * t + 1) & 3) * 2048],
                   W2B + (2 * t + 1) * 4096, wb, nb, lane, false);
    }

    // ---- epilogue: out[tok,:] += gate * (acc + b2), vector red ----
#pragma unroll
    for (int nt = 0; nt < 4; nt++) {
        int col = (nb + nt) * 8 + 2 * cc;
        float b2a = sm[B2_F + col], b2b = sm[B2_F + col + 1];
#pragma unroll
        for (int mt = 0; mt < 4; mt++) {
            float4 f = acc[mt][nt];
            int ra = mt * 16 + gg;
            int rb = ra + 8;
            if (ra < rows) {
                float gt = s_gate[ra];
                red2(out + (size_t)s_tok[ra] * DM + col,
                     gt * (f.x + b2a), gt * (f.y + b2b));
            }
            if (rb < rows) {
                float gt = s_gate[rb];
                red2(out + (size_t)s_tok[rb] * DM + col,
                     gt * (f.z + b2a), gt * (f.w + b2b));
            }
        }
    }
}

// ---------------- launch ----------------
extern "C" void kernel_launch(void* const* d_in, const int* in_sizes, int n_in,
                              void* d_out, int out_size) {
    const float* v0   = (const float*)d_in[0];
    const float* v1   = (const float*)d_in[1];
    const float* v2   = (const float*)d_in[2];
    const float* rw   = (const float*)d_in[3];
    const float* keys = (const float*)d_in[4];
    const float* W1   = (const float*)d_in[5];
    const float* b1   = (const float*)d_in[6];
    const float* W2   = (const float*)d_in[7];
    const float* b2   = (const float*)d_in[8];
    float* out = (float*)d_out;

    static void* cnt_addr = nullptr;
    if (!cnt_addr) cudaGetSymbolAddress(&cnt_addr, g_cnt);

    cudaFuncSetAttribute(ffn_kernel, cudaFuncAttributeMaxDynamicSharedMemorySize,
                         SMEM_BYTES);

    cudaMemsetAsync(cnt_addr, 0, sizeof(int) * NVIEW * NE, 0);

    prep_router_kernel<<<4608, 256, 0, 0>>>(W1, W2, v0, v1, v2, rw, keys, out);

    dim3 fgrid(N_TOK / TM, NE, NVIEW);   // 128 x 16 x 3, most blocks exit early
    ffn_kernel<<<fgrid, 256, SMEM_BYTES, 0>>>(v0, v1, v2, b1, b2, out);
}